// round 7
// baseline (speedup 1.0000x reference)
#include <cuda_runtime.h>
#include <cuda_pipeline.h>
#include <math_constants.h>

#define B_ 4
#define T_ 512
#define D_ 128
#define H_ 64
#define KP (H_ + 4)   // padded K row stride (conflict-free f4 phases)

__device__ float g_Q[B_*T_*H_];
__device__ float g_K[B_*T_*H_];

__device__ __forceinline__ float tanh_fast(float x) {
    float y;
    asm("tanh.approx.f32 %0, %1;" : "=f"(y) : "f"(x));
    return y;
}

// ---------------------------------------------------------------------------
// Kernel 1: Q/K' prep. 8 t-rows/CTA, grid (T/8,B)=256. Full W staged once.
// ---------------------------------------------------------------------------
__global__ __launch_bounds__(256) void prep_kernel(
    const float* __restrict__ input, const float* __restrict__ demo,
    const float* __restrict__ Wt, const float* __restrict__ Wx,
    const float* __restrict__ Wd, const float* __restrict__ bh)
{
    extern __shared__ float dyn[];
    float* sx  = dyn;           // [8][128]
    float* sWt = dyn + 1024;    // [128][64]
    float* sWx = dyn + 9216;    // [128][64]

    const int b   = blockIdx.y;
    const int t0  = blockIdx.x * 8;
    const int tid = threadIdx.x;
    const int h   = tid & 63;
    const int rg  = tid >> 6;

    {
        const float4* gin = (const float4*)(input + (size_t)(b*T_ + t0)*D_);
        __pipeline_memcpy_async(&((float4*)sx)[tid], &gin[tid], 16);
        const float4* gt = (const float4*)Wt;
        const float4* gx = (const float4*)Wx;
        #pragma unroll
        for (int i = 0; i < 8; i++) {
            int idx = tid + 256*i;
            __pipeline_memcpy_async(&((float4*)sWt)[idx], &gt[idx], 16);
            __pipeline_memcpy_async(&((float4*)sWx)[idx], &gx[idx], 16);
        }
        __pipeline_commit();
    }

    float dd = bh[h];
    #pragma unroll
    for (int j = 0; j < 12; j++) dd = fmaf(demo[b*12 + j], Wd[j*H_ + h], dd);

    __pipeline_wait_prior(0);
    __syncthreads();

    float aq0=0.f, ak0=0.f, aq1=0.f, ak1=0.f;
    #pragma unroll 16
    for (int d = 0; d < D_; d++) {
        float wt = sWt[d*H_ + h];
        float wx = sWx[d*H_ + h];
        float x0 = sx[(rg    )*D_ + d];
        float x1 = sx[(rg + 4)*D_ + d];
        aq0 = fmaf(x0, wt, aq0);
        ak0 = fmaf(x0, wx, ak0);
        aq1 = fmaf(x1, wt, aq1);
        ak1 = fmaf(x1, wx, ak1);
    }

    const size_t o0 = (size_t)(b*T_ + t0 + rg    )*H_ + h;
    const size_t o1 = (size_t)(b*T_ + t0 + rg + 4)*H_ + h;
    g_Q[o0] = aq0;  g_K[o0] = ak0 + dd;
    g_Q[o1] = aq1;  g_K[o1] = ak1 + dd;
}

// ---------------------------------------------------------------------------
// Kernel 2: RAW scores (exact R5 version). CTA = 8 t-rows x 128 s-cols.
// grid (T/8, T/128, B) = 1024 CTAs.
// ---------------------------------------------------------------------------
__global__ __launch_bounds__(128, 6) void score_kernel(
    const float* __restrict__ Wa, const float* __restrict__ ba,
    float* __restrict__ out_e)
{
    __shared__ float sQ[8][H_];
    __shared__ float sWa[H_];
    __shared__ float sK[128][KP];

    const int b   = blockIdx.z;
    const int s0  = blockIdx.y * 128;
    const int t0  = blockIdx.x * 8;
    const int tid = threadIdx.x;

    {
        const float4* gq = (const float4*)(g_Q + (size_t)(b*T_ + t0)*H_);
        ((float4*)sQ)[tid] = gq[tid];
        if (tid < H_/4) ((float4*)sWa)[tid] = ((const float4*)Wa)[tid];
    }
    {
        const float4* kp = (const float4*)(g_K + (size_t)(b*T_ + s0)*H_);
        const int j  = tid & 15;
        const int r0 = tid >> 4;
        #pragma unroll
        for (int i = 0; i < 16; i++) {
            int r = r0 + 8*i;
            __pipeline_memcpy_async(&sK[r][4*j], &kp[(size_t)r*16 + j], 16);
        }
        __pipeline_commit();
    }
    __pipeline_wait_prior(0);
    __syncthreads();

    const int s = tid;
    float acc[8] = {0.f,0.f,0.f,0.f,0.f,0.f,0.f,0.f};

    #pragma unroll
    for (int h4 = 0; h4 < H_/4; h4++) {
        float4 k = *(const float4*)&sK[s][4*h4];
        float4 w = ((const float4*)sWa)[h4];
        #pragma unroll
        for (int t = 0; t < 8; t++) {
            float4 q = ((const float4*)sQ[t])[h4];
            acc[t] = fmaf(w.x, tanh_fast(q.x + k.x), acc[t]);
            acc[t] = fmaf(w.y, tanh_fast(q.y + k.y), acc[t]);
            acc[t] = fmaf(w.z, tanh_fast(q.z + k.z), acc[t]);
            acc[t] = fmaf(w.w, tanh_fast(q.w + k.w), acc[t]);
        }
    }

    const float bav = ba[0];
    float* ge = out_e + ((size_t)(b*T_ + t0))*T_ + s0 + s;
    #pragma unroll
    for (int t = 0; t < 8; t++) ge[(size_t)t*T_] = acc[t] + bav;
}

// ---------------------------------------------------------------------------
// Kernel 3: fused softmax + causally-truncated v.
// 512 threads = 16 warps. Warps (r, r+8) pair on row r; warp `half` owns
// even (half=0) / odd (half=1) 32-s chunks -> balanced under truncation.
// v loop truncated at nc = chunks covering s <= t0+7. Grid.x reversed so
// heavy CTAs launch first.
// ---------------------------------------------------------------------------
__global__ __launch_bounds__(512) void sv_kernel(
    const float* __restrict__ input, float* __restrict__ out_e,
    float* __restrict__ out_v)
{
    __shared__ float sIn[32][D_];      // 16 KB chunk
    __shared__ float sVp[8][D_];       // 4 KB partials
    __shared__ float sRed[8][2][2];    // [row][half][{max,sum}]

    const int b    = blockIdx.y;
    const int t0   = ((int)gridDim.x - 1 - (int)blockIdx.x) * 8;  // heavy first
    const int tid  = threadIdx.x;
    const int w    = tid >> 5;
    const int lane = tid & 31;
    const int row  = w & 7;
    const int half = w >> 3;
    const int t    = t0 + row;

    // ---- softmax: warp owns chunks c = half, half+2, ..., half+14 ----
    float vals[8];
    {
        float* ge = out_e + ((size_t)(b*T_ + t))*T_;
        float m = -CUDART_INF_F;
        #pragma unroll
        for (int i = 0; i < 8; i++) {
            vals[i] = ge[(2*i + half)*32 + lane];
            m = fmaxf(m, vals[i]);
        }
        #pragma unroll
        for (int off = 16; off; off >>= 1) m = fmaxf(m, __shfl_xor_sync(0xffffffffu, m, off));
        if (lane == 0) sRed[row][half][0] = m;
        __syncthreads();
        m = fmaxf(sRed[row][0][0], sRed[row][1][0]);   // max over FULL row (pre-mask)

        float sum = 0.f;
        #pragma unroll
        for (int i = 0; i < 8; i++) {
            int s = (2*i + half)*32 + lane;
            float e = __expf(vals[i] - m);
            if (s > t) e = 0.f;                        // causal mask AFTER exp
            vals[i] = e;
            sum += e;
        }
        #pragma unroll
        for (int off = 16; off; off >>= 1) sum += __shfl_xor_sync(0xffffffffu, sum, off);
        if (lane == 0) sRed[row][half][1] = sum;
        __syncthreads();
        float inv = 1.f / (sRed[row][0][1] + sRed[row][1][1] + 1e-7f);
        #pragma unroll
        for (int i = 0; i < 8; i++) {
            float p = vals[i] * inv;
            vals[i] = p;
            ge[(2*i + half)*32 + lane] = p;            // write normalized P
        }
    }

    // ---- v phase: only chunks with any s <= t0+7 ----
    const int nc = (t0 + 7)/32 + 1;    // 1..16
    float4 acc = make_float4(0.f,0.f,0.f,0.f);
    #pragma unroll
    for (int c = 0; c < 16; c++) {
        if (c >= nc) break;
        __syncthreads();
        {   // 1024 f4, 2 per thread, coalesced
            const float4* gin = (const float4*)(input + (size_t)(b*T_ + c*32)*D_);
            ((float4*)sIn)[tid]       = gin[tid];
            ((float4*)sIn)[tid + 512] = gin[tid + 512];
        }
        __syncthreads();
        if ((c & 1) == half) {
            const int i = c >> 1;
            #pragma unroll
            for (int s = 0; s < 32; s++) {
                float p = __shfl_sync(0xffffffffu, vals[i], s);
                float4 x = ((const float4*)sIn[s])[lane];
                acc.x = fmaf(p, x.x, acc.x);
                acc.y = fmaf(p, x.y, acc.y);
                acc.z = fmaf(p, x.z, acc.z);
                acc.w = fmaf(p, x.w, acc.w);
            }
        }
    }

    // ---- combine halves ----
    if (half == 1) *(float4*)&sVp[row][4*lane] = acc;
    __syncthreads();
    if (half == 0) {
        float4 o = *(const float4*)&sVp[row][4*lane];
        o.x += acc.x; o.y += acc.y; o.z += acc.z; o.w += acc.w;
        ((float4*)(out_v + (size_t)(b*T_ + t)*D_))[lane] = o;
    }
}

// ---------------------------------------------------------------------------
extern "C" void kernel_launch(void* const* d_in, const int* in_sizes, int n_in,
                              void* d_out, int out_size)
{
    const float* input = (const float*)d_in[0];
    const float* demo  = (const float*)d_in[1];
    const float* Wt    = (const float*)d_in[2];
    const float* Wx    = (const float*)d_in[3];
    const float* Wd    = (const float*)d_in[4];
    const float* bh    = (const float*)d_in[5];
    const float* Wa    = (const float*)d_in[6];
    const float* ba    = (const float*)d_in[7];

    float* out_v = (float*)d_out;                   // [B,T,D]
    float* out_e = out_v + (size_t)B_ * T_ * D_;    // [B,T,T]

    static int smem_set = 0;
    const int prep_smem = (1024 + 2*8192) * 4;
    if (!smem_set) {
        cudaFuncSetAttribute(prep_kernel, cudaFuncAttributeMaxDynamicSharedMemorySize, prep_smem);
        smem_set = 1;
    }

    dim3 g1(T_/8, B_);
    prep_kernel<<<g1, 256, prep_smem>>>(input, demo, Wt, Wx, Wd, bh);

    dim3 g2(T_/8, T_/128, B_);
    score_kernel<<<g2, 128>>>(Wa, ba, out_e);

    dim3 g3(T_/8, B_);
    sv_kernel<<<g3, 512>>>(input, out_e, out_v);
}

// round 8
// speedup vs baseline: 1.5744x; 1.5744x over previous
#include <cuda_runtime.h>
#include <cuda_pipeline.h>
#include <math_constants.h>

#define B_ 4
#define T_ 512
#define D_ 128
#define H_ 64
#define KP (H_ + 4)   // padded K row stride (conflict-free f4 phases)

__device__ float g_Q[B_*T_*H_];
__device__ float g_K[B_*T_*H_];

__device__ __forceinline__ float tanh_fast(float x) {
    float y;
    asm("tanh.approx.f32 %0, %1;" : "=f"(y) : "f"(x));
    return y;
}

// ---------------------------------------------------------------------------
// Kernel 1: Q/K' prep. 8 t-rows/CTA, grid (T/8,B)=256. Full W staged once.
// ---------------------------------------------------------------------------
__global__ __launch_bounds__(256) void prep_kernel(
    const float* __restrict__ input, const float* __restrict__ demo,
    const float* __restrict__ Wt, const float* __restrict__ Wx,
    const float* __restrict__ Wd, const float* __restrict__ bh)
{
    extern __shared__ float dyn[];
    float* sx  = dyn;           // [8][128]
    float* sWt = dyn + 1024;    // [128][64]
    float* sWx = dyn + 9216;    // [128][64]

    const int b   = blockIdx.y;
    const int t0  = blockIdx.x * 8;
    const int tid = threadIdx.x;
    const int h   = tid & 63;
    const int rg  = tid >> 6;

    {
        const float4* gin = (const float4*)(input + (size_t)(b*T_ + t0)*D_);
        __pipeline_memcpy_async(&((float4*)sx)[tid], &gin[tid], 16);
        const float4* gt = (const float4*)Wt;
        const float4* gx = (const float4*)Wx;
        #pragma unroll
        for (int i = 0; i < 8; i++) {
            int idx = tid + 256*i;
            __pipeline_memcpy_async(&((float4*)sWt)[idx], &gt[idx], 16);
            __pipeline_memcpy_async(&((float4*)sWx)[idx], &gx[idx], 16);
        }
        __pipeline_commit();
    }

    float dd = bh[h];
    #pragma unroll
    for (int j = 0; j < 12; j++) dd = fmaf(demo[b*12 + j], Wd[j*H_ + h], dd);

    __pipeline_wait_prior(0);
    __syncthreads();

    float aq0=0.f, ak0=0.f, aq1=0.f, ak1=0.f;
    #pragma unroll 16
    for (int d = 0; d < D_; d++) {
        float wt = sWt[d*H_ + h];
        float wx = sWx[d*H_ + h];
        float x0 = sx[(rg    )*D_ + d];
        float x1 = sx[(rg + 4)*D_ + d];
        aq0 = fmaf(x0, wt, aq0);
        ak0 = fmaf(x0, wx, ak0);
        aq1 = fmaf(x1, wt, aq1);
        ak1 = fmaf(x1, wx, ak1);
    }

    const size_t o0 = (size_t)(b*T_ + t0 + rg    )*H_ + h;
    const size_t o1 = (size_t)(b*T_ + t0 + rg + 4)*H_ + h;
    g_Q[o0] = aq0;  g_K[o0] = ak0 + dd;
    g_Q[o1] = aq1;  g_K[o1] = ak1 + dd;
}

// ---------------------------------------------------------------------------
// Kernel 2: RAW scores (exact R5 version). CTA = 8 t-rows x 128 s-cols.
// grid (T/8, T/128, B) = 1024 CTAs.
// ---------------------------------------------------------------------------
__global__ __launch_bounds__(128, 6) void score_kernel(
    const float* __restrict__ Wa, const float* __restrict__ ba,
    float* __restrict__ out_e)
{
    __shared__ float sQ[8][H_];
    __shared__ float sWa[H_];
    __shared__ float sK[128][KP];

    const int b   = blockIdx.z;
    const int s0  = blockIdx.y * 128;
    const int t0  = blockIdx.x * 8;
    const int tid = threadIdx.x;

    {
        const float4* gq = (const float4*)(g_Q + (size_t)(b*T_ + t0)*H_);
        ((float4*)sQ)[tid] = gq[tid];
        if (tid < H_/4) ((float4*)sWa)[tid] = ((const float4*)Wa)[tid];
    }
    {
        const float4* kp = (const float4*)(g_K + (size_t)(b*T_ + s0)*H_);
        const int j  = tid & 15;
        const int r0 = tid >> 4;
        #pragma unroll
        for (int i = 0; i < 16; i++) {
            int r = r0 + 8*i;
            __pipeline_memcpy_async(&sK[r][4*j], &kp[(size_t)r*16 + j], 16);
        }
        __pipeline_commit();
    }
    __pipeline_wait_prior(0);
    __syncthreads();

    const int s = tid;
    float acc[8] = {0.f,0.f,0.f,0.f,0.f,0.f,0.f,0.f};

    #pragma unroll
    for (int h4 = 0; h4 < H_/4; h4++) {
        float4 k = *(const float4*)&sK[s][4*h4];
        float4 w = ((const float4*)sWa)[h4];
        #pragma unroll
        for (int t = 0; t < 8; t++) {
            float4 q = ((const float4*)sQ[t])[h4];
            acc[t] = fmaf(w.x, tanh_fast(q.x + k.x), acc[t]);
            acc[t] = fmaf(w.y, tanh_fast(q.y + k.y), acc[t]);
            acc[t] = fmaf(w.z, tanh_fast(q.z + k.z), acc[t]);
            acc[t] = fmaf(w.w, tanh_fast(q.w + k.w), acc[t]);
        }
    }

    const float bav = ba[0];
    float* ge = out_e + ((size_t)(b*T_ + t0))*T_ + s0 + s;
    #pragma unroll
    for (int t = 0; t < 8; t++) ge[(size_t)t*T_] = acc[t] + bav;
}

// ---------------------------------------------------------------------------
// Kernel 3: fused softmax + v (R5 structure). Warp per t-row, 8 rows/CTA,
// 256 threads. ONLY change vs R5: v chunk loop truncated causally
// (P[t,s]=0 for s>t) and grid.x reversed so heavy CTAs launch first.
// ---------------------------------------------------------------------------
__global__ __launch_bounds__(256) void sv_kernel(
    const float* __restrict__ input, float* __restrict__ out_e,
    float* __restrict__ out_v)
{
    __shared__ float sP[8][T_];        // 16 KB
    __shared__ float sIn[32][D_];      // 16 KB

    const int b    = blockIdx.y;
    const int t0   = ((int)gridDim.x - 1 - (int)blockIdx.x) * 8;  // heavy first
    const int tid  = threadIdx.x;
    const int w    = tid >> 5;
    const int lane = tid & 31;
    const int t    = t0 + w;

    // ---- softmax over raw row (max over FULL row, exp, THEN mask s<=t) ----
    {
        float* ge = out_e + ((size_t)(b*T_ + t))*T_;
        float vals[T_/32];
        float m = -CUDART_INF_F;
        #pragma unroll
        for (int i = 0; i < T_/32; i++) {
            vals[i] = ge[lane + 32*i];
            m = fmaxf(m, vals[i]);
        }
        #pragma unroll
        for (int off = 16; off; off >>= 1) m = fmaxf(m, __shfl_xor_sync(0xffffffffu, m, off));
        float sum = 0.f;
        #pragma unroll
        for (int i = 0; i < T_/32; i++) {
            int s = lane + 32*i;
            float e = __expf(vals[i] - m);
            if (s > t) e = 0.f;          // causal mask AFTER exp
            vals[i] = e;
            sum += e;
        }
        #pragma unroll
        for (int off = 16; off; off >>= 1) sum += __shfl_xor_sync(0xffffffffu, sum, off);
        float inv = 1.f / (sum + 1e-7f);
        #pragma unroll
        for (int i = 0; i < T_/32; i++) {
            int s = lane + 32*i;
            float p = vals[i] * inv;
            ge[s]    = p;
            sP[w][s] = p;
        }
        __syncwarp();
    }

    // ---- v phase: only chunks containing s <= t0+7 (P is 0 beyond) ----
    const int nc = t0/32 + 1;          // 1..16 chunks
    float4 acc = make_float4(0.f,0.f,0.f,0.f);
    for (int c = 0; c < nc; c++) {
        __syncthreads();
        {
            const float4* gin = (const float4*)(input + (size_t)(b*T_ + c*32)*D_);
            #pragma unroll
            for (int i = 0; i < 4; i++) ((float4*)sIn)[tid + 256*i] = gin[tid + 256*i];
        }
        __syncthreads();
        #pragma unroll
        for (int s = 0; s < 32; s++) {
            float p = sP[w][c*32 + s];
            float4 x = ((const float4*)sIn[s])[lane];
            acc.x = fmaf(p, x.x, acc.x);
            acc.y = fmaf(p, x.y, acc.y);
            acc.z = fmaf(p, x.z, acc.z);
            acc.w = fmaf(p, x.w, acc.w);
        }
    }
    ((float4*)(out_v + (size_t)(b*T_ + t)*D_))[lane] = acc;
}

// ---------------------------------------------------------------------------
extern "C" void kernel_launch(void* const* d_in, const int* in_sizes, int n_in,
                              void* d_out, int out_size)
{
    const float* input = (const float*)d_in[0];
    const float* demo  = (const float*)d_in[1];
    const float* Wt    = (const float*)d_in[2];
    const float* Wx    = (const float*)d_in[3];
    const float* Wd    = (const float*)d_in[4];
    const float* bh    = (const float*)d_in[5];
    const float* Wa    = (const float*)d_in[6];
    const float* ba    = (const float*)d_in[7];

    float* out_v = (float*)d_out;                   // [B,T,D]
    float* out_e = out_v + (size_t)B_ * T_ * D_;    // [B,T,T]

    static int smem_set = 0;
    const int prep_smem = (1024 + 2*8192) * 4;
    if (!smem_set) {
        cudaFuncSetAttribute(prep_kernel, cudaFuncAttributeMaxDynamicSharedMemorySize, prep_smem);
        smem_set = 1;
    }

    dim3 g1(T_/8, B_);
    prep_kernel<<<g1, 256, prep_smem>>>(input, demo, Wt, Wx, Wd, bh);

    dim3 g2(T_/8, T_/128, B_);
    score_kernel<<<g2, 128>>>(Wa, ba, out_e);

    dim3 g3(T_/8, B_);
    sv_kernel<<<g3, 256>>>(input, out_e, out_v);
}